// round 3
// baseline (speedup 1.0000x reference)
#include <cuda_runtime.h>

#define NN 50000
#define EE 800000
#define RR 850000
#define EPS 1e-5f

// ---------------- static scratch (no runtime allocation) --------------------
__device__ float g_xt[NN * 64];
__device__ float g_dsum[NN * 64];
__device__ float g_dsb[NN * 64];
__device__ float g_s[NN * 64];
__device__ float g_msg[NN * 64];
__device__ float g_msgb[NN * 64];
__device__ float g_agg[NN * 64];
__device__ float g_tpre[NN * 64];
__device__ float g_u[NN * 64];
__device__ float g_h2[(size_t)RR * 64];
__device__ float g_stat[8][64];   // 0/1 bn1 sum/sq, 2/3 bn2, 4/5 bnt, 6/7 bn3
__device__ float g_scale[8][64];  // 0/1 bn1 sc/sh, 2/3 bn2, 4/5 bnt, 6/7 bn3

// ---------------- helpers ----------------------------------------------------
__device__ __forceinline__ void red4(float* addr, float4 v) {
    asm volatile("red.global.add.v4.f32 [%0], {%1,%2,%3,%4};"
                 :: "l"(addr), "f"(v.x), "f"(v.y), "f"(v.z), "f"(v.w) : "memory");
}
__device__ __forceinline__ float4 add4(float4 a, float4 b) {
    return make_float4(a.x + b.x, a.y + b.y, a.z + b.z, a.w + b.w);
}
__device__ __forceinline__ float4 bnrelu4(float4 v, float4 sc, float4 sh) {
    float4 r;
    r.x = fmaxf(fmaf(v.x, sc.x, sh.x), 0.f);
    r.y = fmaxf(fmaf(v.y, sc.y, sh.y), 0.f);
    r.z = fmaxf(fmaf(v.z, sc.z, sh.z), 0.f);
    r.w = fmaxf(fmaf(v.w, sc.w, sh.w), 0.f);
    return r;
}

// ---------------- init: dsum = x, msg = 0, stats = 0 -------------------------
__global__ void k_init(const float4* __restrict__ x4) {
    int idx = blockIdx.x * 256 + threadIdx.x;        // NN*16 = 800000 exact
    ((float4*)g_dsum)[idx] = x4[idx];
    ((float4*)g_msg)[idx] = make_float4(0.f, 0.f, 0.f, 0.f);
    if (idx < 512) (&g_stat[0][0])[idx] = 0.f;
}

// ---------------- dsum[dst] += x[src] ----------------------------------------
__global__ void k_edge_dsum(const float4* __restrict__ x4,
                            const int* __restrict__ src, const int* __restrict__ dst) {
    int idx = blockIdx.x * 256 + threadIdx.x;        // EE*16 exact
    int e = idx >> 4, c4 = idx & 15;
    red4(&g_dsum[(size_t)dst[e] * 64 + c4 * 4], x4[(size_t)src[e] * 16 + c4]);
}

// ---------------- N-row 64x64 GEMM: out = in @ W (+bias) (+=) ----------------
__global__ void __launch_bounds__(128) k_gemm64(float* __restrict__ out,
                                                const float* __restrict__ in,
                                                const float* __restrict__ W,
                                                const float* __restrict__ bias,
                                                int accum) {
    __shared__ float Ws[64][68];
    __shared__ float inS[16][68];
    int tid = threadIdx.x;
    for (int i = tid; i < 4096; i += 128) Ws[i >> 6][i & 63] = W[i];
    int r0 = blockIdx.x * 16;
    for (int i = tid; i < 256; i += 128) {
        int r = i >> 4, c4 = i & 15;
        *(float4*)&inS[r][c4 * 4] = ((const float4*)in)[(size_t)(r0 + r) * 16 + c4];
    }
    __syncthreads();
    int row = tid >> 3, cg = tid & 7, c0 = cg * 8;
    float acc[8];
#pragma unroll
    for (int j = 0; j < 8; j++) acc[j] = bias ? bias[c0 + j] : 0.f;
#pragma unroll 8
    for (int k = 0; k < 64; k++) {
        float a = inS[row][k];
        float4 w0 = *(const float4*)&Ws[k][c0];
        float4 w1 = *(const float4*)&Ws[k][c0 + 4];
        acc[0] = fmaf(a, w0.x, acc[0]); acc[1] = fmaf(a, w0.y, acc[1]);
        acc[2] = fmaf(a, w0.z, acc[2]); acc[3] = fmaf(a, w0.w, acc[3]);
        acc[4] = fmaf(a, w1.x, acc[4]); acc[5] = fmaf(a, w1.y, acc[5]);
        acc[6] = fmaf(a, w1.z, acc[6]); acc[7] = fmaf(a, w1.w, acc[7]);
    }
    float4 o0 = make_float4(acc[0], acc[1], acc[2], acc[3]);
    float4 o1 = make_float4(acc[4], acc[5], acc[6], acc[7]);
    float4* op = (float4*)(out + (size_t)(r0 + row) * 64 + c0);
    if (accum) { o0 = add4(o0, op[0]); o1 = add4(o1, op[1]); }
    op[0] = o0; op[1] = o1;
}

// ---------------- BN1 stats over R virtual rows ------------------------------
__global__ void k_bn1_stats(const int* __restrict__ src, const int* __restrict__ dst,
                            const float* __restrict__ b_unite) {
    __shared__ float st[128];
    if (threadIdx.x < 128) st[threadIdx.x] = 0.f;
    __syncthreads();
    int tid0 = blockIdx.x * 256 + threadIdx.x;
    int stride = gridDim.x * 256;                    // multiple of 16
    int c4 = tid0 & 15;
    float4 b = ((const float4*)b_unite)[c4];
    const float4* xt4 = (const float4*)g_xt;
    const float4* db4 = (const float4*)g_dsb;
    float4 ps = make_float4(0.f, 0.f, 0.f, 0.f);
    float4 pq = make_float4(0.f, 0.f, 0.f, 0.f);
    for (long idx = tid0; idx < (long)RR * 16; idx += stride) {
        long row = idx >> 4;
        int a, d;
        if (row < NN) { a = (int)row; d = a; }
        else { int e = (int)(row - NN); a = src[e]; d = dst[e]; }
        float4 va = xt4[(size_t)a * 16 + c4], vd = db4[(size_t)d * 16 + c4];
        float vx = va.x + vd.x + b.x; ps.x += vx; pq.x += vx * vx;
        float vy = va.y + vd.y + b.y; ps.y += vy; pq.y += vy * vy;
        float vz = va.z + vd.z + b.z; ps.z += vz; pq.z += vz * vz;
        float vw = va.w + vd.w + b.w; ps.w += vw; pq.w += vw * vw;
    }
    atomicAdd(&st[c4 * 4 + 0], ps.x); atomicAdd(&st[64 + c4 * 4 + 0], pq.x);
    atomicAdd(&st[c4 * 4 + 1], ps.y); atomicAdd(&st[64 + c4 * 4 + 1], pq.y);
    atomicAdd(&st[c4 * 4 + 2], ps.z); atomicAdd(&st[64 + c4 * 4 + 2], pq.z);
    atomicAdd(&st[c4 * 4 + 3], ps.w); atomicAdd(&st[64 + c4 * 4 + 3], pq.w);
    __syncthreads();
    if (threadIdx.x < 64) {
        atomicAdd(&g_stat[0][threadIdx.x], st[threadIdx.x]);
        atomicAdd(&g_stat[1][threadIdx.x], st[64 + threadIdx.x]);
    }
}

// ---------------- BN finalize into scale/shift (optionally fold pre-bias) ----
__global__ void k_bn_final(int si, float cnt, const float* __restrict__ g,
                           const float* __restrict__ be, const float* __restrict__ pb,
                           int oi) {
    int c = threadIdx.x;
    float m = g_stat[si][c] / cnt;
    float v = g_stat[si + 1][c] / cnt - m * m;
    float sc = g[c] * rsqrtf(v + EPS);
    float sh = be[c] - m * sc;
    if (pb) sh += pb[c] * sc;
    g_scale[oi][c] = sc;
    g_scale[oi + 1][c] = sh;
}

// ---------------- s[i] = hn(self row i) --------------------------------------
__global__ void k_s_init() {
    int idx = blockIdx.x * 256 + threadIdx.x;        // NN*16 exact
    int c4 = idx & 15;
    float4 va = ((const float4*)g_xt)[idx];
    float4 vd = ((const float4*)g_dsb)[idx];
    float4 sc = ((const float4*)g_scale[0])[c4];
    float4 sh = ((const float4*)g_scale[1])[c4];
    ((float4*)g_s)[idx] = bnrelu4(add4(va, vd), sc, sh);
}

// ---------------- s[dst] += hn(edge row) -------------------------------------
__global__ void k_s_edges(const int* __restrict__ src, const int* __restrict__ dst) {
    int idx = blockIdx.x * 256 + threadIdx.x;
    int e = idx >> 4, c4 = idx & 15;
    int a = src[e], d = dst[e];
    float4 va = ((const float4*)g_xt)[(size_t)a * 16 + c4];
    float4 vd = ((const float4*)g_dsb)[(size_t)d * 16 + c4];
    float4 sc = ((const float4*)g_scale[0])[c4];
    float4 sh = ((const float4*)g_scale[1])[c4];
    red4(&g_s[(size_t)d * 64 + c4 * 4], bnrelu4(add4(va, vd), sc, sh));
}

// ---------------- msg[dst] += s[src] -----------------------------------------
__global__ void k_msg_edges(const int* __restrict__ src, const int* __restrict__ dst) {
    int idx = blockIdx.x * 256 + threadIdx.x;
    int e = idx >> 4, c4 = idx & 15;
    red4(&g_msg[(size_t)dst[e] * 64 + c4 * 4], ((const float4*)g_s)[(size_t)src[e] * 16 + c4]);
}

// ---------------- hot: h2_pre = hn @ Wg_top + msgb[dom]; fused BN2 stats -----
__global__ void __launch_bounds__(256) k_h2(const int* __restrict__ src,
                                            const int* __restrict__ dst,
                                            const float* __restrict__ Wg) {
    __shared__ float Ws[64][68];
    __shared__ float hnS[32][68];
    __shared__ int domS[32];
    __shared__ float statS[128];
    int tid = threadIdx.x;
    for (int i = tid; i < 4096; i += 256) Ws[i >> 6][i & 63] = Wg[i];
    if (tid < 128) statS[tid] = 0.f;
    long r0 = (long)blockIdx.x * 32;
    const float4* xt4 = (const float4*)g_xt;
    const float4* db4 = (const float4*)g_dsb;
    const float4* sc4 = (const float4*)g_scale[0];
    const float4* sh4 = (const float4*)g_scale[1];
    for (int i = tid; i < 512; i += 256) {
        int row = i >> 4, c4 = i & 15;
        long gr = r0 + row;
        float4 v = make_float4(0.f, 0.f, 0.f, 0.f);
        if (gr < RR) {
            int a, d;
            if (gr < NN) { a = (int)gr; d = a; }
            else { int e = (int)(gr - NN); a = src[e]; d = dst[e]; }
            if (c4 == 0) domS[row] = d;
            v = bnrelu4(add4(xt4[(size_t)a * 16 + c4], db4[(size_t)d * 16 + c4]),
                        sc4[c4], sh4[c4]);
        }
        *(float4*)&hnS[row][c4 * 4] = v;
    }
    __syncthreads();
    int row = tid >> 3, cg = tid & 7, c0 = cg * 8;
    float acc[8];
#pragma unroll
    for (int j = 0; j < 8; j++) acc[j] = 0.f;
#pragma unroll 8
    for (int k = 0; k < 64; k++) {
        float a = hnS[row][k];
        float4 w0 = *(const float4*)&Ws[k][c0];
        float4 w1 = *(const float4*)&Ws[k][c0 + 4];
        acc[0] = fmaf(a, w0.x, acc[0]); acc[1] = fmaf(a, w0.y, acc[1]);
        acc[2] = fmaf(a, w0.z, acc[2]); acc[3] = fmaf(a, w0.w, acc[3]);
        acc[4] = fmaf(a, w1.x, acc[4]); acc[5] = fmaf(a, w1.y, acc[5]);
        acc[6] = fmaf(a, w1.z, acc[6]); acc[7] = fmaf(a, w1.w, acc[7]);
    }
    long gr = r0 + row;
    if (gr < RR) {
        int dm = domS[row];
        const float4* mb4 = (const float4*)g_msgb;
        float4 m0 = mb4[(size_t)dm * 16 + cg * 2];
        float4 m1 = mb4[(size_t)dm * 16 + cg * 2 + 1];
        float o[8] = { acc[0] + m0.x, acc[1] + m0.y, acc[2] + m0.z, acc[3] + m0.w,
                       acc[4] + m1.x, acc[5] + m1.y, acc[6] + m1.z, acc[7] + m1.w };
        float4* op = (float4*)(g_h2 + (size_t)gr * 64 + c0);
        op[0] = make_float4(o[0], o[1], o[2], o[3]);
        op[1] = make_float4(o[4], o[5], o[6], o[7]);
#pragma unroll
        for (int j = 0; j < 8; j++) {
            atomicAdd(&statS[c0 + j], o[j]);
            atomicAdd(&statS[64 + c0 + j], o[j] * o[j]);
        }
    }
    __syncthreads();
    if (tid < 64) {
        atomicAdd(&g_stat[2][tid], statS[tid]);
        atomicAdd(&g_stat[3][tid], statS[64 + tid]);
    }
}

// ---------------- agg init: agg[i] = u[i] = relu(bn2(h2_pre[self i])) --------
__global__ void k_agg_init() {
    int idx = blockIdx.x * 256 + threadIdx.x;        // NN*16 exact
    int c4 = idx & 15;
    float4 h = ((const float4*)g_h2)[idx];
    float4 r = bnrelu4(h, ((const float4*)g_scale[2])[c4], ((const float4*)g_scale[3])[c4]);
    ((float4*)g_agg)[idx] = r;
    ((float4*)g_u)[idx] = r;
}

// ---------------- agg[src] += relu(bn2(h2_pre[edge row])) --------------------
__global__ void k_agg_edges(const int* __restrict__ src) {
    int idx = blockIdx.x * 256 + threadIdx.x;
    int e = idx >> 4, c4 = idx & 15;
    float4 h = ((const float4*)g_h2)[(size_t)(NN + e) * 16 + c4];
    float4 r = bnrelu4(h, ((const float4*)g_scale[2])[c4], ((const float4*)g_scale[3])[c4]);
    red4(&g_agg[(size_t)src[e] * 64 + c4 * 4], r);
}

// ---------------- stats of a plain N-row buffer ------------------------------
__global__ void k_stats(const float* __restrict__ in, int n16, int si) {
    __shared__ float st[128];
    if (threadIdx.x < 128) st[threadIdx.x] = 0.f;
    __syncthreads();
    int tid0 = blockIdx.x * 256 + threadIdx.x;
    int stride = gridDim.x * 256;
    int c4 = tid0 & 15;
    float4 ps = make_float4(0.f, 0.f, 0.f, 0.f);
    float4 pq = make_float4(0.f, 0.f, 0.f, 0.f);
    for (int idx = tid0; idx < n16; idx += stride) {
        float4 v = ((const float4*)in)[idx];
        ps.x += v.x; pq.x += v.x * v.x;
        ps.y += v.y; pq.y += v.y * v.y;
        ps.z += v.z; pq.z += v.z * v.z;
        ps.w += v.w; pq.w += v.w * v.w;
    }
    atomicAdd(&st[c4 * 4 + 0], ps.x); atomicAdd(&st[64 + c4 * 4 + 0], pq.x);
    atomicAdd(&st[c4 * 4 + 1], ps.y); atomicAdd(&st[64 + c4 * 4 + 1], pq.y);
    atomicAdd(&st[c4 * 4 + 2], ps.z); atomicAdd(&st[64 + c4 * 4 + 2], pq.z);
    atomicAdd(&st[c4 * 4 + 3], ps.w); atomicAdd(&st[64 + c4 * 4 + 3], pq.w);
    __syncthreads();
    if (threadIdx.x < 64) {
        atomicAdd(&g_stat[si][threadIdx.x], st[threadIdx.x]);
        atomicAdd(&g_stat[si + 1][threadIdx.x], st[64 + threadIdx.x]);
    }
}

// ---------------- relu in-place + stats (for BN3 on relu'd values) -----------
__global__ void k_relu_stats(float* __restrict__ buf, int n16, int si) {
    __shared__ float st[128];
    if (threadIdx.x < 128) st[threadIdx.x] = 0.f;
    __syncthreads();
    int tid0 = blockIdx.x * 256 + threadIdx.x;
    int stride = gridDim.x * 256;
    int c4 = tid0 & 15;
    float4 ps = make_float4(0.f, 0.f, 0.f, 0.f);
    float4 pq = make_float4(0.f, 0.f, 0.f, 0.f);
    for (int idx = tid0; idx < n16; idx += stride) {
        float4 v = ((float4*)buf)[idx];
        v.x = fmaxf(v.x, 0.f); v.y = fmaxf(v.y, 0.f);
        v.z = fmaxf(v.z, 0.f); v.w = fmaxf(v.w, 0.f);
        ((float4*)buf)[idx] = v;
        ps.x += v.x; pq.x += v.x * v.x;
        ps.y += v.y; pq.y += v.y * v.y;
        ps.z += v.z; pq.z += v.z * v.z;
        ps.w += v.w; pq.w += v.w * v.w;
    }
    atomicAdd(&st[c4 * 4 + 0], ps.x); atomicAdd(&st[64 + c4 * 4 + 0], pq.x);
    atomicAdd(&st[c4 * 4 + 1], ps.y); atomicAdd(&st[64 + c4 * 4 + 1], pq.y);
    atomicAdd(&st[c4 * 4 + 2], ps.z); atomicAdd(&st[64 + c4 * 4 + 2], pq.z);
    atomicAdd(&st[c4 * 4 + 3], ps.w); atomicAdd(&st[64 + c4 * 4 + 3], pq.w);
    __syncthreads();
    if (threadIdx.x < 64) {
        atomicAdd(&g_stat[si][threadIdx.x], st[threadIdx.x]);
        atomicAdd(&g_stat[si + 1][threadIdx.x], st[64 + threadIdx.x]);
    }
}

// ---------------- out = relu(in * scale + shift) -----------------------------
__global__ void k_bnrelu(float* __restrict__ out, const float* __restrict__ in, int sidx) {
    int idx = blockIdx.x * 256 + threadIdx.x;        // NN*16 exact
    int c4 = idx & 15;
    float4 v = ((const float4*)in)[idx];
    ((float4*)out)[idx] = bnrelu4(v, ((const float4*)g_scale[0] + (size_t)sidx * 16)[c4],
                                  ((const float4*)g_scale[0] + (size_t)(sidx + 1) * 16)[c4]);
}

extern "C" void kernel_launch(void* const* d_in, const int* in_sizes, int n_in,
                              void* d_out, int out_size) {
    const float* x   = (const float*)d_in[0];
    const int*   ei  = (const int*)d_in[1];
    const int*   src = ei;
    const int*   dst = ei + EE;
    const float* Wu  = (const float*)d_in[2];
    const float* bu  = (const float*)d_in[3];
    const float* g1  = (const float*)d_in[4];
    const float* be1 = (const float*)d_in[5];
    const float* Wg  = (const float*)d_in[6];
    const float* bg  = (const float*)d_in[7];
    const float* g2  = (const float*)d_in[8];
    const float* be2 = (const float*)d_in[9];
    const float* Wt  = (const float*)d_in[10];
    const float* bt  = (const float*)d_in[11];
    const float* Wl  = (const float*)d_in[12];
    const float* bl  = (const float*)d_in[13];
    const float* g3  = (const float*)d_in[14];
    const float* be3 = (const float*)d_in[15];

    static float *p_xt = nullptr, *p_dsum, *p_dsb, *p_s, *p_msg, *p_msgb,
                 *p_agg, *p_tpre, *p_u;
    if (!p_xt) {
        cudaGetSymbolAddress((void**)&p_xt, g_xt);
        cudaGetSymbolAddress((void**)&p_dsum, g_dsum);
        cudaGetSymbolAddress((void**)&p_dsb, g_dsb);
        cudaGetSymbolAddress((void**)&p_s, g_s);
        cudaGetSymbolAddress((void**)&p_msg, g_msg);
        cudaGetSymbolAddress((void**)&p_msgb, g_msgb);
        cudaGetSymbolAddress((void**)&p_agg, g_agg);
        cudaGetSymbolAddress((void**)&p_tpre, g_tpre);
        cudaGetSymbolAddress((void**)&p_u, g_u);
    }

    // unite
    k_init<<<3125, 256>>>((const float4*)x);
    k_edge_dsum<<<50000, 256>>>((const float4*)x, src, dst);
    k_gemm64<<<3125, 128>>>(p_xt, x, Wu, nullptr, 0);
    k_gemm64<<<3125, 128>>>(p_dsb, p_dsum, Wu + 4096, nullptr, 0);
    k_bn1_stats<<<2048, 256>>>(src, dst, bu);
    k_bn_final<<<1, 64>>>(0, (float)RR, g1, be1, bu, 0);

    // gconv
    k_s_init<<<3125, 256>>>();
    k_s_edges<<<50000, 256>>>(src, dst);
    k_msg_edges<<<50000, 256>>>(src, dst);
    k_gemm64<<<3125, 128>>>(p_msgb, p_msg, Wg + 4096, bg, 0);
    k_h2<<<26563, 256>>>(src, dst, Wg);
    k_bn_final<<<1, 64>>>(2, (float)RR, g2, be2, nullptr, 2);

    // transfer
    k_agg_init<<<3125, 256>>>();
    k_agg_edges<<<50000, 256>>>(src);
    k_gemm64<<<3125, 128>>>(p_tpre, p_u, Wt, bt, 0);
    k_gemm64<<<3125, 128>>>(p_tpre, p_agg, Wt + 4096, nullptr, 1);
    k_stats<<<1024, 256>>>(p_tpre, NN * 16, 4);
    k_bn_final<<<1, 64>>>(4, (float)NN, g2, be2, nullptr, 4);
    k_bnrelu<<<3125, 256>>>(p_s, p_tpre, 4);   // t stored in g_s

    // final linear + BN3
    k_gemm64<<<3125, 128>>>(p_u, p_s, Wl, bl, 0);
    k_relu_stats<<<1024, 256>>>(p_u, NN * 16, 6);
    k_bn_final<<<1, 64>>>(6, (float)NN, g3, be3, nullptr, 6);
    k_bnrelu<<<3125, 256>>>((float*)d_out, p_u, 6);
}

// round 4
// speedup vs baseline: 3.2514x; 3.2514x over previous
#include <cuda_runtime.h>

#define NN 50000
#define EE 800000
#define RR 850000
#define EPS 1e-5f
#define GSMEM 51200   // (64*68 + 64*132) * 4 bytes

// ---------------- static scratch (no runtime allocation) --------------------
__device__ float g_xt[NN * 64];
__device__ float g_dsum[NN * 64];
__device__ float g_dsb[NN * 64];
__device__ float g_s[NN * 64];
__device__ float g_msg[NN * 64];
__device__ float g_msgb[NN * 64];
__device__ float g_agg[NN * 64];
__device__ float g_tpre[NN * 64];
__device__ float g_u[NN * 64];
__device__ float g_h2[(size_t)RR * 64];
__device__ float g_stat[8][64];   // 0/1 bn1 sum/sq, 2/3 bn2, 4/5 bnt, 6/7 bn3
__device__ float g_scale[8][64];  // 0/1 bn1 sc/sh, 2/3 bn2, 4/5 bnt, 6/7 bn3

// ---------------- helpers ----------------------------------------------------
__device__ __forceinline__ void red4(float* addr, float4 v) {
    asm volatile("red.global.add.v4.f32 [%0], {%1,%2,%3,%4};"
                 :: "l"(addr), "f"(v.x), "f"(v.y), "f"(v.z), "f"(v.w) : "memory");
}
__device__ __forceinline__ float4 add4(float4 a, float4 b) {
    return make_float4(a.x + b.x, a.y + b.y, a.z + b.z, a.w + b.w);
}
__device__ __forceinline__ float4 bnrelu4(float4 v, float4 sc, float4 sh) {
    float4 r;
    r.x = fmaxf(fmaf(v.x, sc.x, sh.x), 0.f);
    r.y = fmaxf(fmaf(v.y, sc.y, sh.y), 0.f);
    r.z = fmaxf(fmaf(v.z, sc.z, sh.z), 0.f);
    r.w = fmaxf(fmaf(v.w, sc.w, sh.w), 0.f);
    return r;
}

// ---------------- init: dsum = x, msg = 0, stats = 0 -------------------------
__global__ void k_init(const float4* __restrict__ x4) {
    int idx = blockIdx.x * 256 + threadIdx.x;        // NN*16 = 800000 exact
    ((float4*)g_dsum)[idx] = x4[idx];
    ((float4*)g_msg)[idx] = make_float4(0.f, 0.f, 0.f, 0.f);
    if (idx < 512) (&g_stat[0][0])[idx] = 0.f;
}

// ---------------- dsum[dst] += x[src] ----------------------------------------
__global__ void k_edge_dsum(const float4* __restrict__ x4,
                            const int* __restrict__ src, const int* __restrict__ dst) {
    int idx = blockIdx.x * 256 + threadIdx.x;        // EE*16 exact
    int e = idx >> 4, c4 = idx & 15;
    red4(&g_dsum[(size_t)dst[e] * 64 + c4 * 4], x4[(size_t)src[e] * 16 + c4]);
}

// ---------------- N-row 64x64 GEMM, 128 rows/block, 4r x 8c micro-tile -------
// out = [accum? out +] in @ W [+ bias]; optional relu; optional BN stats -> si
__global__ void __launch_bounds__(256) k_gemmN(float* __restrict__ out,
                                               const float* __restrict__ in,
                                               const float* __restrict__ W,
                                               const float* __restrict__ bias,
                                               int accum, int relu, int si) {
    extern __shared__ float dynS[];
    float* Ws = dynS;              // [64][68]
    float* inT = dynS + 64 * 68;   // [64][132]  k-major transposed activations
    __shared__ float statS[128];
    int tid = threadIdx.x;
    for (int i = tid; i < 4096; i += 256) Ws[(i >> 6) * 68 + (i & 63)] = W[i];
    if (tid < 128) statS[tid] = 0.f;
    int base = blockIdx.x * 128;
    const float4* in4 = (const float4*)in;
    for (int i = tid; i < 2048; i += 256) {
        int r = i & 127, c4 = i >> 7;
        float4 v = make_float4(0.f, 0.f, 0.f, 0.f);
        if (base + r < NN) v = in4[(size_t)(base + r) * 16 + c4];
        int c = c4 * 4;
        inT[c * 132 + r] = v.x; inT[(c + 1) * 132 + r] = v.y;
        inT[(c + 2) * 132 + r] = v.z; inT[(c + 3) * 132 + r] = v.w;
    }
    __syncthreads();
    int rg = tid >> 3, cg = tid & 7;
    int r0 = rg * 4, c0 = cg * 8;
    float bj[8];
#pragma unroll
    for (int j = 0; j < 8; j++) bj[j] = bias ? bias[c0 + j] : 0.f;
    float acc[4][8];
#pragma unroll
    for (int rr = 0; rr < 4; rr++)
#pragma unroll
        for (int j = 0; j < 8; j++) acc[rr][j] = bj[j];
#pragma unroll 4
    for (int k = 0; k < 64; k++) {
        float4 a4 = *(const float4*)&inT[k * 132 + r0];
        float4 w0 = *(const float4*)&Ws[k * 68 + c0];
        float4 w1 = *(const float4*)&Ws[k * 68 + c0 + 4];
        float av[4] = { a4.x, a4.y, a4.z, a4.w };
        float wv[8] = { w0.x, w0.y, w0.z, w0.w, w1.x, w1.y, w1.z, w1.w };
#pragma unroll
        for (int rr = 0; rr < 4; rr++)
#pragma unroll
            for (int j = 0; j < 8; j++)
                acc[rr][j] = fmaf(av[rr], wv[j], acc[rr][j]);
    }
    float lsum[8], lsq[8];
#pragma unroll
    for (int j = 0; j < 8; j++) { lsum[j] = 0.f; lsq[j] = 0.f; }
#pragma unroll
    for (int rr = 0; rr < 4; rr++) {
        int gr = base + r0 + rr;
        if (gr >= NN) break;
        float4* op = (float4*)(out + (size_t)gr * 64 + c0);
        float o[8];
#pragma unroll
        for (int j = 0; j < 8; j++) o[j] = acc[rr][j];
        if (accum) {
            float4 e0 = op[0], e1 = op[1];
            o[0] += e0.x; o[1] += e0.y; o[2] += e0.z; o[3] += e0.w;
            o[4] += e1.x; o[5] += e1.y; o[6] += e1.z; o[7] += e1.w;
        }
        if (relu) {
#pragma unroll
            for (int j = 0; j < 8; j++) o[j] = fmaxf(o[j], 0.f);
        }
        if (si >= 0) {
#pragma unroll
            for (int j = 0; j < 8; j++) { lsum[j] += o[j]; lsq[j] += o[j] * o[j]; }
        }
        op[0] = make_float4(o[0], o[1], o[2], o[3]);
        op[1] = make_float4(o[4], o[5], o[6], o[7]);
    }
    if (si >= 0) {
        int lane = tid & 31;
#pragma unroll
        for (int j = 0; j < 8; j++) {
            float s_ = lsum[j], q_ = lsq[j];
            s_ += __shfl_xor_sync(0xFFFFFFFFu, s_, 8);
            s_ += __shfl_xor_sync(0xFFFFFFFFu, s_, 16);
            q_ += __shfl_xor_sync(0xFFFFFFFFu, q_, 8);
            q_ += __shfl_xor_sync(0xFFFFFFFFu, q_, 16);
            if (lane < 8) {
                atomicAdd(&statS[c0 + j], s_);
                atomicAdd(&statS[64 + c0 + j], q_);
            }
        }
        __syncthreads();
        if (tid < 64) {
            atomicAdd(&g_stat[si][tid], statS[tid]);
            atomicAdd(&g_stat[si + 1][tid], statS[64 + tid]);
        }
    }
}

// ---------------- BN1 stats over R virtual rows ------------------------------
__global__ void k_bn1_stats(const int* __restrict__ src, const int* __restrict__ dst,
                            const float* __restrict__ b_unite) {
    __shared__ float st[128];
    if (threadIdx.x < 128) st[threadIdx.x] = 0.f;
    __syncthreads();
    int tid0 = blockIdx.x * 256 + threadIdx.x;
    int stride = gridDim.x * 256;                    // multiple of 16
    int c4 = tid0 & 15;
    float4 b = ((const float4*)b_unite)[c4];
    const float4* xt4 = (const float4*)g_xt;
    const float4* db4 = (const float4*)g_dsb;
    float4 ps = make_float4(0.f, 0.f, 0.f, 0.f);
    float4 pq = make_float4(0.f, 0.f, 0.f, 0.f);
    for (long idx = tid0; idx < (long)RR * 16; idx += stride) {
        long row = idx >> 4;
        int a, d;
        if (row < NN) { a = (int)row; d = a; }
        else { int e = (int)(row - NN); a = src[e]; d = dst[e]; }
        float4 va = xt4[(size_t)a * 16 + c4], vd = db4[(size_t)d * 16 + c4];
        float vx = va.x + vd.x + b.x; ps.x += vx; pq.x += vx * vx;
        float vy = va.y + vd.y + b.y; ps.y += vy; pq.y += vy * vy;
        float vz = va.z + vd.z + b.z; ps.z += vz; pq.z += vz * vz;
        float vw = va.w + vd.w + b.w; ps.w += vw; pq.w += vw * vw;
    }
    atomicAdd(&st[c4 * 4 + 0], ps.x); atomicAdd(&st[64 + c4 * 4 + 0], pq.x);
    atomicAdd(&st[c4 * 4 + 1], ps.y); atomicAdd(&st[64 + c4 * 4 + 1], pq.y);
    atomicAdd(&st[c4 * 4 + 2], ps.z); atomicAdd(&st[64 + c4 * 4 + 2], pq.z);
    atomicAdd(&st[c4 * 4 + 3], ps.w); atomicAdd(&st[64 + c4 * 4 + 3], pq.w);
    __syncthreads();
    if (threadIdx.x < 64) {
        atomicAdd(&g_stat[0][threadIdx.x], st[threadIdx.x]);
        atomicAdd(&g_stat[1][threadIdx.x], st[64 + threadIdx.x]);
    }
}

// ---------------- BN finalize into scale/shift (optionally fold pre-bias) ----
__global__ void k_bn_final(int si, float cnt, const float* __restrict__ g,
                           const float* __restrict__ be, const float* __restrict__ pb,
                           int oi) {
    int c = threadIdx.x;
    float m = g_stat[si][c] / cnt;
    float v = g_stat[si + 1][c] / cnt - m * m;
    float sc = g[c] * rsqrtf(v + EPS);
    float sh = be[c] - m * sc;
    if (pb) sh += pb[c] * sc;
    g_scale[oi][c] = sc;
    g_scale[oi + 1][c] = sh;
}

// ---------------- s[i] = hn(self row i) --------------------------------------
__global__ void k_s_init() {
    int idx = blockIdx.x * 256 + threadIdx.x;        // NN*16 exact
    int c4 = idx & 15;
    float4 va = ((const float4*)g_xt)[idx];
    float4 vd = ((const float4*)g_dsb)[idx];
    float4 sc = ((const float4*)g_scale[0])[c4];
    float4 sh = ((const float4*)g_scale[1])[c4];
    ((float4*)g_s)[idx] = bnrelu4(add4(va, vd), sc, sh);
}

// ---------------- s[dst] += hn(edge row) -------------------------------------
__global__ void k_s_edges(const int* __restrict__ src, const int* __restrict__ dst) {
    int idx = blockIdx.x * 256 + threadIdx.x;
    int e = idx >> 4, c4 = idx & 15;
    int a = src[e], d = dst[e];
    float4 va = ((const float4*)g_xt)[(size_t)a * 16 + c4];
    float4 vd = ((const float4*)g_dsb)[(size_t)d * 16 + c4];
    float4 sc = ((const float4*)g_scale[0])[c4];
    float4 sh = ((const float4*)g_scale[1])[c4];
    red4(&g_s[(size_t)d * 64 + c4 * 4], bnrelu4(add4(va, vd), sc, sh));
}

// ---------------- msg[dst] += s[src] -----------------------------------------
__global__ void k_msg_edges(const int* __restrict__ src, const int* __restrict__ dst) {
    int idx = blockIdx.x * 256 + threadIdx.x;
    int e = idx >> 4, c4 = idx & 15;
    red4(&g_msg[(size_t)dst[e] * 64 + c4 * 4], ((const float4*)g_s)[(size_t)src[e] * 16 + c4]);
}

// ---------------- hot: h2_pre = hn @ Wg_top + msgb[dom]; fused BN2 stats -----
// 4 tiles x 128 rows per block; weights loaded once; 4r x 8c micro-tile.
__global__ void __launch_bounds__(256) k_h2(const int* __restrict__ src,
                                            const int* __restrict__ dst,
                                            const float* __restrict__ Wg) {
    extern __shared__ float dynS[];
    float* Ws = dynS;              // [64][68]
    float* hnT = dynS + 64 * 68;   // [64][132]
    __shared__ int domS[128];
    __shared__ float statS[128];
    int tid = threadIdx.x;
    for (int i = tid; i < 4096; i += 256) Ws[(i >> 6) * 68 + (i & 63)] = Wg[i];
    if (tid < 128) statS[tid] = 0.f;
    int rg = tid >> 3, cg = tid & 7;
    int r0 = rg * 4, c0 = cg * 8;
    const float4* xt4 = (const float4*)g_xt;
    const float4* db4 = (const float4*)g_dsb;
    const float4* sc4 = (const float4*)g_scale[0];
    const float4* sh4 = (const float4*)g_scale[1];
    const float4* mb4 = (const float4*)g_msgb;
    float lsum[8], lsq[8];
#pragma unroll
    for (int j = 0; j < 8; j++) { lsum[j] = 0.f; lsq[j] = 0.f; }
    __syncthreads();

    for (int t = 0; t < 4; t++) {
        long base = ((long)blockIdx.x * 4 + t) * 128;
        if (base >= RR) break;
        // build 128-row hn tile (k-major) + domain ids
        for (int i = tid; i < 2048; i += 256) {
            int r = i & 127, c4 = i >> 7;
            long gr = base + r;
            float4 v = make_float4(0.f, 0.f, 0.f, 0.f);
            int d = 0;
            if (gr < RR) {
                int a;
                if (gr < NN) { a = (int)gr; d = a; }
                else { int e = (int)(gr - NN); a = src[e]; d = dst[e]; }
                v = bnrelu4(add4(xt4[(size_t)a * 16 + c4], db4[(size_t)d * 16 + c4]),
                            sc4[c4], sh4[c4]);
            }
            if (c4 == 0) domS[r] = d;
            int c = c4 * 4;
            hnT[c * 132 + r] = v.x; hnT[(c + 1) * 132 + r] = v.y;
            hnT[(c + 2) * 132 + r] = v.z; hnT[(c + 3) * 132 + r] = v.w;
        }
        __syncthreads();
        float acc[4][8];
#pragma unroll
        for (int rr = 0; rr < 4; rr++)
#pragma unroll
            for (int j = 0; j < 8; j++) acc[rr][j] = 0.f;
#pragma unroll 4
        for (int k = 0; k < 64; k++) {
            float4 a4 = *(const float4*)&hnT[k * 132 + r0];
            float4 w0 = *(const float4*)&Ws[k * 68 + c0];
            float4 w1 = *(const float4*)&Ws[k * 68 + c0 + 4];
            float av[4] = { a4.x, a4.y, a4.z, a4.w };
            float wv[8] = { w0.x, w0.y, w0.z, w0.w, w1.x, w1.y, w1.z, w1.w };
#pragma unroll
            for (int rr = 0; rr < 4; rr++)
#pragma unroll
                for (int j = 0; j < 8; j++)
                    acc[rr][j] = fmaf(av[rr], wv[j], acc[rr][j]);
        }
#pragma unroll
        for (int rr = 0; rr < 4; rr++) {
            long gr = base + r0 + rr;
            if (gr >= RR) break;
            int dm = domS[r0 + rr];
            float4 m0 = mb4[(size_t)dm * 16 + cg * 2];
            float4 m1 = mb4[(size_t)dm * 16 + cg * 2 + 1];
            float o[8] = { acc[rr][0] + m0.x, acc[rr][1] + m0.y,
                           acc[rr][2] + m0.z, acc[rr][3] + m0.w,
                           acc[rr][4] + m1.x, acc[rr][5] + m1.y,
                           acc[rr][6] + m1.z, acc[rr][7] + m1.w };
#pragma unroll
            for (int j = 0; j < 8; j++) { lsum[j] += o[j]; lsq[j] += o[j] * o[j]; }
            float4* op = (float4*)(g_h2 + (size_t)gr * 64 + c0);
            op[0] = make_float4(o[0], o[1], o[2], o[3]);
            op[1] = make_float4(o[4], o[5], o[6], o[7]);
        }
        __syncthreads();
    }
    // block-level BN2 stat reduction
    int lane = tid & 31;
#pragma unroll
    for (int j = 0; j < 8; j++) {
        float s_ = lsum[j], q_ = lsq[j];
        s_ += __shfl_xor_sync(0xFFFFFFFFu, s_, 8);
        s_ += __shfl_xor_sync(0xFFFFFFFFu, s_, 16);
        q_ += __shfl_xor_sync(0xFFFFFFFFu, q_, 8);
        q_ += __shfl_xor_sync(0xFFFFFFFFu, q_, 16);
        if (lane < 8) {
            atomicAdd(&statS[c0 + j], s_);
            atomicAdd(&statS[64 + c0 + j], q_);
        }
    }
    __syncthreads();
    if (tid < 64) {
        atomicAdd(&g_stat[2][tid], statS[tid]);
        atomicAdd(&g_stat[3][tid], statS[64 + tid]);
    }
}

// ---------------- agg init: agg[i] = u[i] = relu(bn2(h2_pre[self i])) --------
__global__ void k_agg_init() {
    int idx = blockIdx.x * 256 + threadIdx.x;        // NN*16 exact
    int c4 = idx & 15;
    float4 h = ((const float4*)g_h2)[idx];
    float4 r = bnrelu4(h, ((const float4*)g_scale[2])[c4], ((const float4*)g_scale[3])[c4]);
    ((float4*)g_agg)[idx] = r;
    ((float4*)g_u)[idx] = r;
}

// ---------------- agg[src] += relu(bn2(h2_pre[edge row])) --------------------
__global__ void k_agg_edges(const int* __restrict__ src) {
    int idx = blockIdx.x * 256 + threadIdx.x;
    int e = idx >> 4, c4 = idx & 15;
    float4 h = ((const float4*)g_h2)[(size_t)(NN + e) * 16 + c4];
    float4 r = bnrelu4(h, ((const float4*)g_scale[2])[c4], ((const float4*)g_scale[3])[c4]);
    red4(&g_agg[(size_t)src[e] * 64 + c4 * 4], r);
}

// ---------------- out = relu(in * scale + shift) -----------------------------
__global__ void k_bnrelu(float* __restrict__ out, const float* __restrict__ in, int sidx) {
    int idx = blockIdx.x * 256 + threadIdx.x;        // NN*16 exact
    int c4 = idx & 15;
    float4 v = ((const float4*)in)[idx];
    ((float4*)out)[idx] = bnrelu4(v, ((const float4*)g_scale[0] + (size_t)sidx * 16)[c4],
                                  ((const float4*)g_scale[0] + (size_t)(sidx + 1) * 16)[c4]);
}

extern "C" void kernel_launch(void* const* d_in, const int* in_sizes, int n_in,
                              void* d_out, int out_size) {
    const float* x   = (const float*)d_in[0];
    const int*   ei  = (const int*)d_in[1];
    const int*   src = ei;
    const int*   dst = ei + EE;
    const float* Wu  = (const float*)d_in[2];
    const float* bu  = (const float*)d_in[3];
    const float* g1  = (const float*)d_in[4];
    const float* be1 = (const float*)d_in[5];
    const float* Wg  = (const float*)d_in[6];
    const float* bg  = (const float*)d_in[7];
    const float* g2  = (const float*)d_in[8];
    const float* be2 = (const float*)d_in[9];
    const float* Wt  = (const float*)d_in[10];
    const float* bt  = (const float*)d_in[11];
    const float* Wl  = (const float*)d_in[12];
    const float* bl  = (const float*)d_in[13];
    const float* g3  = (const float*)d_in[14];
    const float* be3 = (const float*)d_in[15];

    static float *p_xt = nullptr, *p_dsum, *p_dsb, *p_s, *p_msg, *p_msgb,
                 *p_agg, *p_tpre, *p_u;
    if (!p_xt) {
        cudaGetSymbolAddress((void**)&p_xt, g_xt);
        cudaGetSymbolAddress((void**)&p_dsum, g_dsum);
        cudaGetSymbolAddress((void**)&p_dsb, g_dsb);
        cudaGetSymbolAddress((void**)&p_s, g_s);
        cudaGetSymbolAddress((void**)&p_msg, g_msg);
        cudaGetSymbolAddress((void**)&p_msgb, g_msgb);
        cudaGetSymbolAddress((void**)&p_agg, g_agg);
        cudaGetSymbolAddress((void**)&p_tpre, g_tpre);
        cudaGetSymbolAddress((void**)&p_u, g_u);
        cudaFuncSetAttribute(k_gemmN, cudaFuncAttributeMaxDynamicSharedMemorySize, GSMEM);
        cudaFuncSetAttribute(k_h2, cudaFuncAttributeMaxDynamicSharedMemorySize, GSMEM);
    }

    // unite
    k_init<<<3125, 256>>>((const float4*)x);
    k_edge_dsum<<<50000, 256>>>((const float4*)x, src, dst);
    k_gemmN<<<391, 256, GSMEM>>>(p_xt, x, Wu, nullptr, 0, 0, -1);
    k_gemmN<<<391, 256, GSMEM>>>(p_dsb, p_dsum, Wu + 4096, nullptr, 0, 0, -1);
    k_bn1_stats<<<2048, 256>>>(src, dst, bu);
    k_bn_final<<<1, 64>>>(0, (float)RR, g1, be1, bu, 0);

    // gconv
    k_s_init<<<3125, 256>>>();
    k_s_edges<<<50000, 256>>>(src, dst);
    k_msg_edges<<<50000, 256>>>(src, dst);
    k_gemmN<<<391, 256, GSMEM>>>(p_msgb, p_msg, Wg + 4096, bg, 0, 0, -1);
    k_h2<<<1661, 256, GSMEM>>>(src, dst, Wg);
    k_bn_final<<<1, 64>>>(2, (float)RR, g2, be2, nullptr, 2);

    // transfer
    k_agg_init<<<3125, 256>>>();
    k_agg_edges<<<50000, 256>>>(src);
    k_gemmN<<<391, 256, GSMEM>>>(p_tpre, p_u, Wt, bt, 0, 0, -1);
    k_gemmN<<<391, 256, GSMEM>>>(p_tpre, p_agg, Wt + 4096, nullptr, 1, 0, 4);
    k_bn_final<<<1, 64>>>(4, (float)NN, g2, be2, nullptr, 4);
    k_bnrelu<<<3125, 256>>>(p_s, p_tpre, 4);   // t stored in g_s

    // final linear + BN3
    k_gemmN<<<391, 256, GSMEM>>>(p_u, p_s, Wl, bl, 0, 1, 6);
    k_bn_final<<<1, 64>>>(6, (float)NN, g3, be3, nullptr, 6);
    k_bnrelu<<<3125, 256>>>((float*)d_out, p_u, 6);
}

// round 5
// speedup vs baseline: 3.5135x; 1.0806x over previous
#include <cuda_runtime.h>

#define NN 50000
#define EE 800000
#define RR 850000
#define EPS 1e-5f
#define GSMEM 51200   // (64*68 + 64*132) * 4 bytes

// ---------------- static scratch (no runtime allocation) --------------------
__device__ float g_xt[NN * 64];
__device__ float g_dsum[NN * 64];
__device__ float g_dsb[NN * 64];
__device__ float g_msg[NN * 64];
__device__ float g_msgb[NN * 64];
__device__ float g_agg[NN * 64];
__device__ float g_tpre[NN * 64];
__device__ float g_u[NN * 64];
__device__ float g_sA[NN * 64];
__device__ float g_h2[(size_t)RR * 64];
__device__ float g_stat[8][64];   // 0/1 bn1 sum/sq, 2/3 bn2, 4/5 bnt, 6/7 bn3
__device__ float g_scale[8][64];  // 0/1 bn1 sc/sh, 2/3 bn2, 4/5 bnt, 6/7 bn3

// ---------------- helpers ----------------------------------------------------
__device__ __forceinline__ void red4(float* addr, float4 v) {
    asm volatile("red.global.add.v4.f32 [%0], {%1,%2,%3,%4};"
                 :: "l"(addr), "f"(v.x), "f"(v.y), "f"(v.z), "f"(v.w) : "memory");
}
__device__ __forceinline__ void fma2(unsigned long long& d,
                                     unsigned long long a, unsigned long long b) {
    asm("fma.rn.f32x2 %0, %1, %2, %0;" : "+l"(d) : "l"(a), "l"(b));
}
__device__ __forceinline__ unsigned long long dup2(float x) {
    unsigned long long r;
    asm("mov.b64 %0, {%1, %1};" : "=l"(r) : "f"(x));
    return r;
}
__device__ __forceinline__ unsigned long long pack2(float x, float y) {
    unsigned long long r;
    asm("mov.b64 %0, {%1, %2};" : "=l"(r) : "f"(x), "f"(y));
    return r;
}
__device__ __forceinline__ float2 unpack2(unsigned long long v) {
    float2 r;
    asm("mov.b64 {%0, %1}, %2;" : "=f"(r.x), "=f"(r.y) : "l"(v));
    return r;
}
__device__ __forceinline__ float4 add4(float4 a, float4 b) {
    return make_float4(a.x + b.x, a.y + b.y, a.z + b.z, a.w + b.w);
}
__device__ __forceinline__ float4 bnrelu4(float4 v, float4 sc, float4 sh) {
    float4 r;
    r.x = fmaxf(fmaf(v.x, sc.x, sh.x), 0.f);
    r.y = fmaxf(fmaf(v.y, sc.y, sh.y), 0.f);
    r.z = fmaxf(fmaf(v.z, sc.z, sh.z), 0.f);
    r.w = fmaxf(fmaf(v.w, sc.w, sh.w), 0.f);
    return r;
}

// ---------------- init: dsum = x, msg = 0, stats = 0 -------------------------
__global__ void k_init(const float4* __restrict__ x4) {
    int idx = blockIdx.x * 256 + threadIdx.x;        // NN*16 = 800000 exact
    ((float4*)g_dsum)[idx] = x4[idx];
    ((float4*)g_msg)[idx] = make_float4(0.f, 0.f, 0.f, 0.f);
    if (idx < 512) (&g_stat[0][0])[idx] = 0.f;
}

// ---------------- dsum[dst] += x[src] ----------------------------------------
__global__ void k_edge_dsum(const float4* __restrict__ x4,
                            const int* __restrict__ src, const int* __restrict__ dst) {
    int idx = blockIdx.x * 256 + threadIdx.x;        // EE*16 exact
    int e = idx >> 4, c4 = idx & 15;
    red4(&g_dsum[(size_t)dst[e] * 64 + c4 * 4], x4[(size_t)src[e] * 16 + c4]);
}

// ---------------- N-row GEMM: out = in1@W1 [+ in2@W2] [+bias]; f32x2 FMA -----
// optional input transform (bnrelu with g_scale[insc]) on in1 tile load;
// optional output relu; optional BN stats into g_stat[si].
__global__ void __launch_bounds__(256) k_gemm2(float* __restrict__ out,
                                               const float* __restrict__ in1,
                                               const float* __restrict__ W1,
                                               const float* __restrict__ in2,
                                               const float* __restrict__ W2,
                                               const float* __restrict__ bias,
                                               int relu, int si, int insc) {
    extern __shared__ float dynS[];
    float* Ws = dynS;              // [64][68]
    float* inT = dynS + 64 * 68;   // [64][132]  k-major transposed activations
    __shared__ float statS[128];
    int tid = threadIdx.x;
    if (tid < 128) statS[tid] = 0.f;
    int base = blockIdx.x * 128;
    int rg = tid >> 3, cg = tid & 7;
    int r0 = rg * 4, c0 = cg * 8;
    unsigned long long acc[4][4];
#pragma unroll
    for (int rr = 0; rr < 4; rr++)
#pragma unroll
        for (int jp = 0; jp < 4; jp++)
            acc[rr][jp] = bias ? pack2(bias[c0 + jp * 2], bias[c0 + jp * 2 + 1]) : 0ull;

#pragma unroll 1
    for (int p = 0; p < 2; p++) {
        const float* in = p ? in2 : in1;
        const float* W = p ? W2 : W1;
        if (!in) break;
        if (p) __syncthreads();                      // protect smem reuse
        for (int i = tid; i < 4096; i += 256) Ws[(i >> 6) * 68 + (i & 63)] = W[i];
        const float4* in4 = (const float4*)in;
        int xf = (p == 0 && insc >= 0);
        for (int i = tid; i < 2048; i += 256) {
            int r = i & 127, c4 = i >> 7;
            float4 v = make_float4(0.f, 0.f, 0.f, 0.f);
            if (base + r < NN) {
                v = in4[(size_t)(base + r) * 16 + c4];
                if (xf) v = bnrelu4(v, ((const float4*)g_scale[insc])[c4],
                                    ((const float4*)g_scale[insc + 1])[c4]);
            }
            int c = c4 * 4;
            inT[c * 132 + r] = v.x; inT[(c + 1) * 132 + r] = v.y;
            inT[(c + 2) * 132 + r] = v.z; inT[(c + 3) * 132 + r] = v.w;
        }
        __syncthreads();
#pragma unroll 4
        for (int k = 0; k < 64; k++) {
            float4 a4 = *(const float4*)&inT[k * 132 + r0];
            ulonglong2 w01 = *(const ulonglong2*)&Ws[k * 68 + c0];
            ulonglong2 w23 = *(const ulonglong2*)&Ws[k * 68 + c0 + 4];
            unsigned long long wp[4] = { w01.x, w01.y, w23.x, w23.y };
            unsigned long long ap[4] = { dup2(a4.x), dup2(a4.y), dup2(a4.z), dup2(a4.w) };
#pragma unroll
            for (int rr = 0; rr < 4; rr++)
#pragma unroll
                for (int jp = 0; jp < 4; jp++)
                    fma2(acc[rr][jp], ap[rr], wp[jp]);
        }
    }
    float lsum[8], lsq[8];
#pragma unroll
    for (int j = 0; j < 8; j++) { lsum[j] = 0.f; lsq[j] = 0.f; }
#pragma unroll
    for (int rr = 0; rr < 4; rr++) {
        int gr = base + r0 + rr;
        if (gr >= NN) break;
        float o[8];
#pragma unroll
        for (int jp = 0; jp < 4; jp++) {
            float2 u = unpack2(acc[rr][jp]);
            o[jp * 2] = u.x; o[jp * 2 + 1] = u.y;
        }
        if (relu) {
#pragma unroll
            for (int j = 0; j < 8; j++) o[j] = fmaxf(o[j], 0.f);
        }
        if (si >= 0) {
#pragma unroll
            for (int j = 0; j < 8; j++) { lsum[j] += o[j]; lsq[j] += o[j] * o[j]; }
        }
        float4* op = (float4*)(out + (size_t)gr * 64 + c0);
        op[0] = make_float4(o[0], o[1], o[2], o[3]);
        op[1] = make_float4(o[4], o[5], o[6], o[7]);
    }
    if (si >= 0) {
        int lane = tid & 31;
#pragma unroll
        for (int j = 0; j < 8; j++) {
            float s_ = lsum[j], q_ = lsq[j];
            s_ += __shfl_xor_sync(0xFFFFFFFFu, s_, 8);
            s_ += __shfl_xor_sync(0xFFFFFFFFu, s_, 16);
            q_ += __shfl_xor_sync(0xFFFFFFFFu, q_, 8);
            q_ += __shfl_xor_sync(0xFFFFFFFFu, q_, 16);
            if (lane < 8) {
                atomicAdd(&statS[c0 + j], s_);
                atomicAdd(&statS[64 + c0 + j], q_);
            }
        }
        __syncthreads();
        if (tid < 64) {
            atomicAdd(&g_stat[si][tid], statS[tid]);
            atomicAdd(&g_stat[si + 1][tid], statS[64 + tid]);
        }
    }
}

// ---------------- BN1 stats over R virtual rows ------------------------------
__global__ void k_bn1_stats(const int* __restrict__ src, const int* __restrict__ dst,
                            const float* __restrict__ b_unite) {
    __shared__ float st[128];
    if (threadIdx.x < 128) st[threadIdx.x] = 0.f;
    __syncthreads();
    int tid0 = blockIdx.x * 256 + threadIdx.x;
    int stride = gridDim.x * 256;                    // multiple of 16
    int c4 = tid0 & 15;
    float4 b = ((const float4*)b_unite)[c4];
    const float4* xt4 = (const float4*)g_xt;
    const float4* db4 = (const float4*)g_dsb;
    float4 ps = make_float4(0.f, 0.f, 0.f, 0.f);
    float4 pq = make_float4(0.f, 0.f, 0.f, 0.f);
    for (long idx = tid0; idx < (long)RR * 16; idx += stride) {
        long row = idx >> 4;
        int a, d;
        if (row < NN) { a = (int)row; d = a; }
        else { int e = (int)(row - NN); a = src[e]; d = dst[e]; }
        float4 va = xt4[(size_t)a * 16 + c4], vd = db4[(size_t)d * 16 + c4];
        float vx = va.x + vd.x + b.x; ps.x += vx; pq.x += vx * vx;
        float vy = va.y + vd.y + b.y; ps.y += vy; pq.y += vy * vy;
        float vz = va.z + vd.z + b.z; ps.z += vz; pq.z += vz * vz;
        float vw = va.w + vd.w + b.w; ps.w += vw; pq.w += vw * vw;
    }
    atomicAdd(&st[c4 * 4 + 0], ps.x); atomicAdd(&st[64 + c4 * 4 + 0], pq.x);
    atomicAdd(&st[c4 * 4 + 1], ps.y); atomicAdd(&st[64 + c4 * 4 + 1], pq.y);
    atomicAdd(&st[c4 * 4 + 2], ps.z); atomicAdd(&st[64 + c4 * 4 + 2], pq.z);
    atomicAdd(&st[c4 * 4 + 3], ps.w); atomicAdd(&st[64 + c4 * 4 + 3], pq.w);
    __syncthreads();
    if (threadIdx.x < 64) {
        atomicAdd(&g_stat[0][threadIdx.x], st[threadIdx.x]);
        atomicAdd(&g_stat[1][threadIdx.x], st[64 + threadIdx.x]);
    }
}

// ---------------- BN finalize into scale/shift (optionally fold pre-bias) ----
__global__ void k_bn_final(int si, float cnt, const float* __restrict__ g,
                           const float* __restrict__ be, const float* __restrict__ pb,
                           int oi) {
    int c = threadIdx.x;
    float m = g_stat[si][c] / cnt;
    float v = g_stat[si + 1][c] / cnt - m * m;
    float sc = g[c] * rsqrtf(v + EPS);
    float sh = be[c] - m * sc;
    if (pb) sh += pb[c] * sc;
    g_scale[oi][c] = sc;
    g_scale[oi + 1][c] = sh;
}

// ---------------- s[i] = hn(self row i) --------------------------------------
__global__ void k_s_init() {
    int idx = blockIdx.x * 256 + threadIdx.x;        // NN*16 exact
    int c4 = idx & 15;
    float4 va = ((const float4*)g_xt)[idx];
    float4 vd = ((const float4*)g_dsb)[idx];
    float4 sc = ((const float4*)g_scale[0])[c4];
    float4 sh = ((const float4*)g_scale[1])[c4];
    ((float4*)g_sA)[idx] = bnrelu4(add4(va, vd), sc, sh);
}

// ---------------- s[dst] += hn(edge row) -------------------------------------
__global__ void k_s_edges(const int* __restrict__ src, const int* __restrict__ dst) {
    int idx = blockIdx.x * 256 + threadIdx.x;
    int e = idx >> 4, c4 = idx & 15;
    int a = src[e], d = dst[e];
    float4 va = ((const float4*)g_xt)[(size_t)a * 16 + c4];
    float4 vd = ((const float4*)g_dsb)[(size_t)d * 16 + c4];
    float4 sc = ((const float4*)g_scale[0])[c4];
    float4 sh = ((const float4*)g_scale[1])[c4];
    red4(&g_sA[(size_t)d * 64 + c4 * 4], bnrelu4(add4(va, vd), sc, sh));
}

// ---------------- msg[dst] += s[src] -----------------------------------------
__global__ void k_msg_edges(const int* __restrict__ src, const int* __restrict__ dst) {
    int idx = blockIdx.x * 256 + threadIdx.x;
    int e = idx >> 4, c4 = idx & 15;
    red4(&g_msg[(size_t)dst[e] * 64 + c4 * 4], ((const float4*)g_sA)[(size_t)src[e] * 16 + c4]);
}

// ---------------- hot: h2_pre = hn @ Wg_top + msgb[dom]; fused BN2 stats -----
// 4 tiles x 128 rows per block; f32x2 packed FMA.
__global__ void __launch_bounds__(256) k_h2(const int* __restrict__ src,
                                            const int* __restrict__ dst,
                                            const float* __restrict__ Wg) {
    extern __shared__ float dynS[];
    float* Ws = dynS;              // [64][68]
    float* hnT = dynS + 64 * 68;   // [64][132]
    __shared__ int domS[128];
    __shared__ float statS[128];
    int tid = threadIdx.x;
    for (int i = tid; i < 4096; i += 256) Ws[(i >> 6) * 68 + (i & 63)] = Wg[i];
    if (tid < 128) statS[tid] = 0.f;
    int rg = tid >> 3, cg = tid & 7;
    int r0 = rg * 4, c0 = cg * 8;
    const float4* xt4 = (const float4*)g_xt;
    const float4* db4 = (const float4*)g_dsb;
    const float4* sc4 = (const float4*)g_scale[0];
    const float4* sh4 = (const float4*)g_scale[1];
    const float4* mb4 = (const float4*)g_msgb;
    float lsum[8], lsq[8];
#pragma unroll
    for (int j = 0; j < 8; j++) { lsum[j] = 0.f; lsq[j] = 0.f; }
    __syncthreads();

    for (int t = 0; t < 4; t++) {
        long base = ((long)blockIdx.x * 4 + t) * 128;
        if (base >= RR) break;
        for (int i = tid; i < 2048; i += 256) {
            int r = i & 127, c4 = i >> 7;
            long gr = base + r;
            float4 v = make_float4(0.f, 0.f, 0.f, 0.f);
            int d = 0;
            if (gr < RR) {
                int a;
                if (gr < NN) { a = (int)gr; d = a; }
                else { int e = (int)(gr - NN); a = src[e]; d = dst[e]; }
                v = bnrelu4(add4(xt4[(size_t)a * 16 + c4], db4[(size_t)d * 16 + c4]),
                            sc4[c4], sh4[c4]);
            }
            if (c4 == 0) domS[r] = d;
            int c = c4 * 4;
            hnT[c * 132 + r] = v.x; hnT[(c + 1) * 132 + r] = v.y;
            hnT[(c + 2) * 132 + r] = v.z; hnT[(c + 3) * 132 + r] = v.w;
        }
        __syncthreads();
        unsigned long long acc[4][4];
#pragma unroll
        for (int rr = 0; rr < 4; rr++)
#pragma unroll
            for (int jp = 0; jp < 4; jp++) acc[rr][jp] = 0ull;
#pragma unroll 4
        for (int k = 0; k < 64; k++) {
            float4 a4 = *(const float4*)&hnT[k * 132 + r0];
            ulonglong2 w01 = *(const ulonglong2*)&Ws[k * 68 + c0];
            ulonglong2 w23 = *(const ulonglong2*)&Ws[k * 68 + c0 + 4];
            unsigned long long wp[4] = { w01.x, w01.y, w23.x, w23.y };
            unsigned long long ap[4] = { dup2(a4.x), dup2(a4.y), dup2(a4.z), dup2(a4.w) };
#pragma unroll
            for (int rr = 0; rr < 4; rr++)
#pragma unroll
                for (int jp = 0; jp < 4; jp++)
                    fma2(acc[rr][jp], ap[rr], wp[jp]);
        }
#pragma unroll
        for (int rr = 0; rr < 4; rr++) {
            long gr = base + r0 + rr;
            if (gr >= RR) break;
            int dm = domS[r0 + rr];
            float4 m0 = mb4[(size_t)dm * 16 + cg * 2];
            float4 m1 = mb4[(size_t)dm * 16 + cg * 2 + 1];
            float mv[8] = { m0.x, m0.y, m0.z, m0.w, m1.x, m1.y, m1.z, m1.w };
            float o[8];
#pragma unroll
            for (int jp = 0; jp < 4; jp++) {
                float2 u = unpack2(acc[rr][jp]);
                o[jp * 2] = u.x + mv[jp * 2];
                o[jp * 2 + 1] = u.y + mv[jp * 2 + 1];
            }
#pragma unroll
            for (int j = 0; j < 8; j++) { lsum[j] += o[j]; lsq[j] += o[j] * o[j]; }
            float4* op = (float4*)(g_h2 + (size_t)gr * 64 + c0);
            op[0] = make_float4(o[0], o[1], o[2], o[3]);
            op[1] = make_float4(o[4], o[5], o[6], o[7]);
        }
        __syncthreads();
    }
    int lane = tid & 31;
#pragma unroll
    for (int j = 0; j < 8; j++) {
        float s_ = lsum[j], q_ = lsq[j];
        s_ += __shfl_xor_sync(0xFFFFFFFFu, s_, 8);
        s_ += __shfl_xor_sync(0xFFFFFFFFu, s_, 16);
        q_ += __shfl_xor_sync(0xFFFFFFFFu, q_, 8);
        q_ += __shfl_xor_sync(0xFFFFFFFFu, q_, 16);
        if (lane < 8) {
            atomicAdd(&statS[c0 + j], s_);
            atomicAdd(&statS[64 + c0 + j], q_);
        }
    }
    __syncthreads();
    if (tid < 64) {
        atomicAdd(&g_stat[2][tid], statS[tid]);
        atomicAdd(&g_stat[3][tid], statS[64 + tid]);
    }
}

// ---------------- agg init: agg[i] = u[i] = relu(bn2(h2_pre[self i])) --------
__global__ void k_agg_init() {
    int idx = blockIdx.x * 256 + threadIdx.x;        // NN*16 exact
    int c4 = idx & 15;
    float4 h = ((const float4*)g_h2)[idx];
    float4 r = bnrelu4(h, ((const float4*)g_scale[2])[c4], ((const float4*)g_scale[3])[c4]);
    ((float4*)g_agg)[idx] = r;
    ((float4*)g_u)[idx] = r;
}

// ---------------- agg[src] += relu(bn2(h2_pre[edge row])) --------------------
__global__ void k_agg_edges(const int* __restrict__ src) {
    int idx = blockIdx.x * 256 + threadIdx.x;
    int e = idx >> 4, c4 = idx & 15;
    float4 h = ((const float4*)g_h2)[(size_t)(NN + e) * 16 + c4];
    float4 r = bnrelu4(h, ((const float4*)g_scale[2])[c4], ((const float4*)g_scale[3])[c4]);
    red4(&g_agg[(size_t)src[e] * 64 + c4 * 4], r);
}

// ---------------- out = relu(in * scale + shift) -----------------------------
__global__ void k_bnrelu(float* __restrict__ out, const float* __restrict__ in, int sidx) {
    int idx = blockIdx.x * 256 + threadIdx.x;        // NN*16 exact
    int c4 = idx & 15;
    float4 v = ((const float4*)in)[idx];
    ((float4*)out)[idx] = bnrelu4(v, ((const float4*)g_scale[0] + (size_t)sidx * 16)[c4],
                                  ((const float4*)g_scale[0] + (size_t)(sidx + 1) * 16)[c4]);
}

extern "C" void kernel_launch(void* const* d_in, const int* in_sizes, int n_in,
                              void* d_out, int out_size) {
    const float* x   = (const float*)d_in[0];
    const int*   ei  = (const int*)d_in[1];
    const int*   src = ei;
    const int*   dst = ei + EE;
    const float* Wu  = (const float*)d_in[2];
    const float* bu  = (const float*)d_in[3];
    const float* g1  = (const float*)d_in[4];
    const float* be1 = (const float*)d_in[5];
    const float* Wg  = (const float*)d_in[6];
    const float* bg  = (const float*)d_in[7];
    const float* g2  = (const float*)d_in[8];
    const float* be2 = (const float*)d_in[9];
    const float* Wt  = (const float*)d_in[10];
    const float* bt  = (const float*)d_in[11];
    const float* Wl  = (const float*)d_in[12];
    const float* bl  = (const float*)d_in[13];
    const float* g3  = (const float*)d_in[14];
    const float* be3 = (const float*)d_in[15];

    static float *p_xt = nullptr, *p_dsum, *p_dsb, *p_msg, *p_msgb,
                 *p_agg, *p_tpre, *p_u;
    if (!p_xt) {
        cudaGetSymbolAddress((void**)&p_xt, g_xt);
        cudaGetSymbolAddress((void**)&p_dsum, g_dsum);
        cudaGetSymbolAddress((void**)&p_dsb, g_dsb);
        cudaGetSymbolAddress((void**)&p_msg, g_msg);
        cudaGetSymbolAddress((void**)&p_msgb, g_msgb);
        cudaGetSymbolAddress((void**)&p_agg, g_agg);
        cudaGetSymbolAddress((void**)&p_tpre, g_tpre);
        cudaGetSymbolAddress((void**)&p_u, g_u);
        cudaFuncSetAttribute(k_gemm2, cudaFuncAttributeMaxDynamicSharedMemorySize, GSMEM);
        cudaFuncSetAttribute(k_h2, cudaFuncAttributeMaxDynamicSharedMemorySize, GSMEM);
    }

    // unite
    k_init<<<3125, 256>>>((const float4*)x);
    k_edge_dsum<<<50000, 256>>>((const float4*)x, src, dst);
    k_gemm2<<<391, 256, GSMEM>>>(p_xt, x, Wu, nullptr, nullptr, nullptr, 0, -1, -1);
    k_gemm2<<<391, 256, GSMEM>>>(p_dsb, p_dsum, Wu + 4096, nullptr, nullptr, nullptr, 0, -1, -1);
    k_bn1_stats<<<2048, 256>>>(src, dst, bu);
    k_bn_final<<<1, 64>>>(0, (float)RR, g1, be1, bu, 0);

    // gconv
    k_s_init<<<3125, 256>>>();
    k_s_edges<<<50000, 256>>>(src, dst);
    k_msg_edges<<<50000, 256>>>(src, dst);
    k_gemm2<<<391, 256, GSMEM>>>(p_msgb, p_msg, Wg + 4096, nullptr, nullptr, bg, 0, -1, -1);
    k_h2<<<1661, 256, GSMEM>>>(src, dst, Wg);
    k_bn_final<<<1, 64>>>(2, (float)RR, g2, be2, nullptr, 2);

    // transfer (fused dual GEMM: tpre = u@Wt_top + agg@Wt_bot + bt, BNt stats)
    k_agg_init<<<3125, 256>>>();
    k_agg_edges<<<50000, 256>>>(src);
    k_gemm2<<<391, 256, GSMEM>>>(p_tpre, p_u, Wt, p_agg, Wt + 4096, bt, 0, 4, -1);
    k_bn_final<<<1, 64>>>(4, (float)NN, g2, be2, nullptr, 4);

    // final linear with fused input bnrelu(t) transform; relu + BN3 stats
    k_gemm2<<<391, 256, GSMEM>>>(p_u, p_tpre, Wl, nullptr, nullptr, bl, 1, 6, 4);
    k_bn_final<<<1, 64>>>(6, (float)NN, g3, be3, nullptr, 6);
    k_bnrelu<<<3125, 256>>>((float*)d_out, p_u, 6);
}